// round 3
// baseline (speedup 1.0000x reference)
#include <cuda_runtime.h>

// Problem constants (fixed shapes from reference)
#define BB   2
#define HD   4
#define HH   128
#define WW   128
#define KS   7
#define KK   49    // 7*7
#define NSP  9
#define SS   64

// Warp-per-pixel kernel.
// Lane l owns k1 = l and k2 = l + 32 (k2 valid only for l < 17).
// Gathers: for each sp, one plane; the 32 lanes' window elements span only
// ~5-7 image rows of that plane -> few L1 wavefronts per gather instruction.
__global__ __launch_bounds__(256)
void attn_reweight_kernel(const float* __restrict__ attn,
                          const float* __restrict__ sims,
                          const int*   __restrict__ sinds,
                          float*       __restrict__ out)
{
    const int warp = blockIdx.x * (blockDim.x >> 5) + (threadIdx.x >> 5);
    const int lane = threadIdx.x & 31;

    // warp -> (b, h, w);  exactly B*H*W warps launched
    const int b  = warp >> 14;        // / (128*128)
    const int hw = warp & 16383;
    const int h  = hw >> 7;
    const int w  = hw & 127;

    const int hs = min(max(h - KS / 2, 0), HH - KS);
    const int ws = min(max(w - KS / 2, 0), WW - KS);

    const int  k1 = lane;
    const int  k2 = lane + 32;
    const bool v2 = (k2 < KK);
    const int  r1 = k1 / KS, c1 = k1 % KS;
    const int  r2 = k2 / KS, c2 = k2 % KS;

    const int sind_base  = ((b * HH + h) * WW + w) * NSP;
    const int batch_base = b * SS * HH * WW;

    // ---- gather p windows (9 planes) ----
    float p1[NSP], p2[NSP];
#pragma unroll
    for (int sp = 0; sp < NSP; ++sp) {
        const int gid = __ldg(&sinds[sind_base + sp]);           // uniform across warp
        const float* pl = sims + batch_base + gid * (HH * WW);
        p1[sp] = __ldg(&pl[(hs + r1) * WW + (ws + c1)]);
        p2[sp] = v2 ? __ldg(&pl[(hs + r2) * WW + (ws + c2)]) : 0.0f;
    }

    // ---- pi_sp = sims[b, gid, h, w] == window value at center index (free via shfl) ----
    const int cidx = (h - hs) * KS + (w - ws);   // in [0,48], uniform across warp
    float pi[NSP];
    if (cidx < 32) {
#pragma unroll
        for (int sp = 0; sp < NSP; ++sp)
            pi[sp] = __shfl_sync(0xffffffffu, p1[sp], cidx);
    } else {
#pragma unroll
        for (int sp = 0; sp < NSP; ++sp)
            pi[sp] = __shfl_sync(0xffffffffu, p2[sp], cidx - 32);
    }

    // ---- per-head compute ----
#pragma unroll
    for (int hd = 0; hd < HD; ++hd) {
        const int abase = (((b * HD + hd) * HH + h) * WW + w) * KK;

        const float av1 = __ldg(&attn[abase + k1]);
        const float av2 = v2 ? __ldg(&attn[abase + k2]) : -1e30f;

        // max over 49 values
        float m = fmaxf(av1, av2);
#pragma unroll
        for (int o = 16; o > 0; o >>= 1)
            m = fmaxf(m, __shfl_xor_sync(0xffffffffu, m, o));

        const float a1 = __expf(av1 - m);
        const float a2 = v2 ? __expf(av2 - m) : 0.0f;

        // denominators: d[sp] = sum_k a_k * p_sp[k]
        float d[NSP];
#pragma unroll
        for (int sp = 0; sp < NSP; ++sp)
            d[sp] = fmaf(a1, p1[sp], a2 * p2[sp]);
#pragma unroll
        for (int o = 16; o > 0; o >>= 1) {
#pragma unroll
            for (int sp = 0; sp < NSP; ++sp)
                d[sp] += __shfl_xor_sync(0xffffffffu, d[sp], o);
        }

        // w_sp = pi_sp / (eps + d_sp); paired reciprocals cut MUFU 9 -> 5
        float wsp[NSP];
#pragma unroll
        for (int sp = 0; sp < NSP; ++sp)
            d[sp] += 1e-10f;
#pragma unroll
        for (int q = 0; q < 4; ++q) {
            const float prod = d[2 * q] * d[2 * q + 1];
            float rp;
            asm("rcp.approx.f32 %0, %1;" : "=f"(rp) : "f"(prod));
            wsp[2 * q]     = pi[2 * q]     * (rp * d[2 * q + 1]);
            wsp[2 * q + 1] = pi[2 * q + 1] * (rp * d[2 * q]);
        }
        {
            float r8;
            asm("rcp.approx.f32 %0, %1;" : "=f"(r8) : "f"(d[8]));
            wsp[8] = pi[8] * r8;
        }

        // out_k = a_k * sum_sp w_sp * p_sp[k]
        float o1 = 0.0f, o2 = 0.0f;
#pragma unroll
        for (int sp = 0; sp < NSP; ++sp) {
            o1 = fmaf(wsp[sp], p1[sp], o1);
            o2 = fmaf(wsp[sp], p2[sp], o2);
        }
        out[abase + k1] = a1 * o1;
        if (v2) out[abase + k2] = a2 * o2;
    }
}

extern "C" void kernel_launch(void* const* d_in, const int* in_sizes, int n_in,
                              void* d_out, int out_size)
{
    const float* attn  = (const float*)d_in[0];
    const float* sims  = (const float*)d_in[1];
    const int*   sinds = (const int*)d_in[2];
    float*       out   = (float*)d_out;

    const int warps_needed = BB * HH * WW;          // 32768
    const int threads      = 256;                   // 8 warps / CTA
    const int blocks       = warps_needed / (threads / 32);  // 4096
    attn_reweight_kernel<<<blocks, threads>>>(attn, sims, sinds, out);
}

// round 4
// speedup vs baseline: 1.4083x; 1.4083x over previous
#include <cuda_runtime.h>

// Problem constants (fixed shapes)
#define BB   2
#define HD   4
#define HH   128
#define WW   128
#define KS   7
#define KK   49
#define NSP  9
#define SS   64
#define PLANE (HH * WW)

// Two pixels per warp: lanes 0-15 -> pixel (h, w0), lanes 16-31 -> pixel (h, w0+1).
// Lane t (=lane&15) owns k in {t, t+16, t+32}; lane t==15 additionally owns k=48.
// All reductions are 16-lane butterflies (xor 8,4,2,1), serving both pixels at once.
__global__ __launch_bounds__(256)
void attn_reweight_kernel(const float* __restrict__ attn,
                          const float* __restrict__ sims,
                          const int*   __restrict__ sinds,
                          float*       __restrict__ out)
{
    const int warpid = blockIdx.x * (blockDim.x >> 5) + (threadIdx.x >> 5);
    const int lane   = threadIdx.x & 31;
    const int half   = lane >> 4;
    const int t      = lane & 15;

    // warp -> pixel pair (same row, adjacent w)
    const int pix0 = warpid << 1;
    const int b    = pix0 >> 14;          // / (128*128)
    const int idx  = pix0 & 16383;
    const int h    = idx >> 7;
    const int w    = (idx & 127) + half;  // idx&127 is even

    const int hs = min(max(h - KS / 2, 0), HH - KS);
    const int ws = min(max(w - KS / 2, 0), WW - KS);

    const int  k0 = t, k1 = t + 16, k2 = t + 32;
    const bool last = (t == 15);

    // window offsets within a plane (per lane, loop-invariant)
    const int off0 = (hs + k0 / KS) * WW + ws + k0 % KS;
    const int off1 = (hs + k1 / KS) * WW + ws + k1 % KS;
    const int off2 = (hs + k2 / KS) * WW + ws + k2 % KS;
    const int off3 = (hs + 6) * WW + (ws + 6);        // k = 48 -> (6,6)
    const int offc = h * WW + w;                      // center -> pi

    const float* sb    = sims + b * (SS * PLANE);
    const int    sbase = ((b * HH + h) * WW + w) * NSP;

    // ---- gather: 9 planes x {3 window vals (+1 on t==15) + center} ----
    float p0[NSP], p1v[NSP], p2[NSP], p3[NSP], pi[NSP];
#pragma unroll
    for (int sp = 0; sp < NSP; ++sp) {
        const int gid = __ldg(&sinds[sbase + sp]);     // uniform per half-warp
        const float* pl = sb + gid * PLANE;
        p0[sp]  = __ldg(&pl[off0]);
        p1v[sp] = __ldg(&pl[off1]);
        p2[sp]  = __ldg(&pl[off2]);
        p3[sp]  = last ? __ldg(&pl[off3]) : 0.0f;
        pi[sp]  = __ldg(&pl[offc]);                    // guaranteed L1 hit (in window)
    }

    // ---- per-head compute ----
#pragma unroll
    for (int hd = 0; hd < HD; ++hd) {
        const int base = (((b * HD + hd) * HH + h) * WW + w) * KK;
        const float* ab = attn + base;

        const float av0 = __ldg(ab + k0);
        const float av1 = __ldg(ab + k1);
        const float av2 = __ldg(ab + k2);
        const float av3 = last ? __ldg(ab + 48) : -1e30f;

        // max over the 49 values of this pixel (16-lane butterfly)
        float m = fmaxf(fmaxf(av0, av1), fmaxf(av2, av3));
#pragma unroll
        for (int o = 8; o > 0; o >>= 1)
            m = fmaxf(m, __shfl_xor_sync(0xffffffffu, m, o));

        const float a0 = __expf(av0 - m);
        const float a1 = __expf(av1 - m);
        const float a2 = __expf(av2 - m);
        const float a3 = __expf(av3 - m);   // exact 0 on non-last lanes

        // denominators d[sp] = sum_k a_k * p_sp[k]
        float d[NSP];
#pragma unroll
        for (int sp = 0; sp < NSP; ++sp) {
            float acc = fmaf(a0, p0[sp], a1 * p1v[sp]);
            acc = fmaf(a2, p2[sp], acc);
            acc = fmaf(a3, p3[sp], acc);
            d[sp] = acc;
        }
#pragma unroll
        for (int o = 8; o > 0; o >>= 1) {
#pragma unroll
            for (int sp = 0; sp < NSP; ++sp)
                d[sp] += __shfl_xor_sync(0xffffffffu, d[sp], o);
        }

        // w_sp = pi_sp / (eps + d_sp); paired reciprocals: 5 MUFU for 9 divisions
        float wsp[NSP];
#pragma unroll
        for (int sp = 0; sp < NSP; ++sp)
            d[sp] += 1e-10f;
#pragma unroll
        for (int q = 0; q < 4; ++q) {
            const float prod = d[2 * q] * d[2 * q + 1];
            float rp;
            asm("rcp.approx.f32 %0, %1;" : "=f"(rp) : "f"(prod));
            wsp[2 * q]     = pi[2 * q]     * (rp * d[2 * q + 1]);
            wsp[2 * q + 1] = pi[2 * q + 1] * (rp * d[2 * q]);
        }
        {
            float r8;
            asm("rcp.approx.f32 %0, %1;" : "=f"(r8) : "f"(d[8]));
            wsp[8] = pi[8] * r8;
        }

        // out_k = a_k * sum_sp w_sp * p_sp[k]
        float o0 = 0.0f, o1 = 0.0f, o2 = 0.0f, o3 = 0.0f;
#pragma unroll
        for (int sp = 0; sp < NSP; ++sp) {
            o0 = fmaf(wsp[sp], p0[sp],  o0);
            o1 = fmaf(wsp[sp], p1v[sp], o1);
            o2 = fmaf(wsp[sp], p2[sp],  o2);
            o3 = fmaf(wsp[sp], p3[sp],  o3);
        }

        float* ob = out + base;
        ob[k0] = a0 * o0;
        ob[k1] = a1 * o1;
        ob[k2] = a2 * o2;
        if (last) ob[48] = a3 * o3;
    }
}

extern "C" void kernel_launch(void* const* d_in, const int* in_sizes, int n_in,
                              void* d_out, int out_size)
{
    const float* attn  = (const float*)d_in[0];
    const float* sims  = (const float*)d_in[1];
    const int*   sinds = (const int*)d_in[2];
    float*       out   = (float*)d_out;

    const int warps   = BB * HH * WW / 2;        // 16384 warps (2 pixels each)
    const int threads = 256;                     // 8 warps / CTA
    const int blocks  = warps / (threads / 32);  // 2048
    attn_reweight_kernel<<<blocks, threads>>>(attn, sims, sinds, out);
}